// round 1
// baseline (speedup 1.0000x reference)
#include <cuda_runtime.h>
#include <cuda_bf16.h>
#include <math.h>

#define N_NODES 50000
#define N_EDGES 800000
#define NFEAT   128
#define NHID    96
#define NCLASS  40

// Scratch (allocation-free): h = post-GEMM features, a = aggregation / current x
__device__ __align__(16) float g_h[N_NODES * NHID];
__device__ __align__(16) float g_a[N_NODES * NHID];

// ---------------------------------------------------------------------------
// GEMM: out[r,c] = sum_k X[r,k] * W[k,c],  out is g_h, cols = 96
// block: (24, 16) = 384 threads, each thread computes 4 adjacent columns
// ---------------------------------------------------------------------------
template <int K>
__global__ void gemm_kernel(const float* __restrict__ X,
                            const float* __restrict__ W) {
    __shared__ float Ws[K * NHID];
    int tid = threadIdx.y * 24 + threadIdx.x;
    for (int i = tid; i < K * NHID; i += 384) Ws[i] = W[i];
    __syncthreads();

    int row = blockIdx.x * 16 + threadIdx.y;
    if (row >= N_NODES) return;
    const float* xr = X + (size_t)row * K;
    int c4 = threadIdx.x * 4;

    float a0 = 0.f, a1 = 0.f, a2 = 0.f, a3 = 0.f;
#pragma unroll
    for (int k0 = 0; k0 < K; k0 += 4) {
        float4 xv = *reinterpret_cast<const float4*>(xr + k0);
        float xs[4] = {xv.x, xv.y, xv.z, xv.w};
#pragma unroll
        for (int j = 0; j < 4; j++) {
            float4 w = *reinterpret_cast<const float4*>(&Ws[(k0 + j) * NHID + c4]);
            a0 += xs[j] * w.x;
            a1 += xs[j] * w.y;
            a2 += xs[j] * w.z;
            a3 += xs[j] * w.w;
        }
    }
    float4 o = make_float4(a0, a1, a2, a3);
    *reinterpret_cast<float4*>(&g_h[(size_t)row * NHID + c4]) = o;
}

// ---------------------------------------------------------------------------
// Zero the aggregation buffer (float4 stores)
// ---------------------------------------------------------------------------
__global__ void zero_agg_kernel() {
    int i = blockIdx.x * blockDim.x + threadIdx.x;
    int n4 = (N_NODES * NHID) / 4;
    if (i < n4) {
        reinterpret_cast<float4*>(g_a)[i] = make_float4(0.f, 0.f, 0.f, 0.f);
    }
}

// ---------------------------------------------------------------------------
// Scatter: for each edge e, agg[dst[e]] += h[src[e]] * ew[e]
// One thread per (edge, float4-chunk). 96 floats/row = 24 chunks.
// Uses red.global.add.v4.f32 (one L2 atomic per 16B).
// ---------------------------------------------------------------------------
__global__ void scatter_kernel(const int* __restrict__ src,
                               const int* __restrict__ dst,
                               const float* __restrict__ ew) {
    int tid = blockIdx.x * blockDim.x + threadIdx.x;
    const int total = N_EDGES * 24;
    if (tid >= total) return;
    int e = tid / 24;
    int c = tid - e * 24;
    int s = src[e];
    int d = dst[e];
    float w = ew[e];
    float4 v = *reinterpret_cast<const float4*>(&g_h[(size_t)s * NHID + c * 4]);
    v.x *= w; v.y *= w; v.z *= w; v.w *= w;
    float* p = &g_a[(size_t)d * NHID + c * 4];
    asm volatile("red.global.add.v4.f32 [%0], {%1, %2, %3, %4};"
                 :: "l"(p), "f"(v.x), "f"(v.y), "f"(v.z), "f"(v.w)
                 : "memory");
}

// ---------------------------------------------------------------------------
// In-place: x = relu( (x + bias) / max(||x + bias||_2, eps) ), one warp/node
// ---------------------------------------------------------------------------
__global__ void norm_kernel(const float* __restrict__ bias) {
    int gwarp = (blockIdx.x * blockDim.x + threadIdx.x) >> 5;
    int lane = threadIdx.x & 31;
    if (gwarp >= N_NODES) return;
    float* row = &g_a[(size_t)gwarp * NHID];

    float v0 = row[lane]      + bias[lane];
    float v1 = row[lane + 32] + bias[lane + 32];
    float v2 = row[lane + 64] + bias[lane + 64];
    float s = v0 * v0 + v1 * v1 + v2 * v2;
#pragma unroll
    for (int o = 16; o; o >>= 1) s += __shfl_xor_sync(0xFFFFFFFFu, s, o);
    float inv = 1.0f / fmaxf(sqrtf(s), 1e-12f);
    row[lane]      = fmaxf(v0 * inv, 0.f);
    row[lane + 32] = fmaxf(v1 * inv, 0.f);
    row[lane + 64] = fmaxf(v2 * inv, 0.f);
}

// ---------------------------------------------------------------------------
// Head: copy emb, logits = emb @ lin_W + lin_b, probs = softmax(logits)
// One warp per node, 4 warps per block. lin_W staged in smem.
// ---------------------------------------------------------------------------
__global__ void head_kernel(const float* __restrict__ linW,
                            const float* __restrict__ linb,
                            float* __restrict__ out) {
    __shared__ float Ws[NHID * NCLASS];  // 96*40
    __shared__ float bs[NCLASS];
    __shared__ float esh[4][NHID];

    int tid = threadIdx.x;
    for (int i = tid; i < NHID * NCLASS; i += 128) Ws[i] = linW[i];
    if (tid < NCLASS) bs[tid] = linb[tid];
    __syncthreads();

    int wid = tid >> 5, lane = tid & 31;
    int node = blockIdx.x * 4 + wid;  // 50000 = 12500 * 4, always valid

    const size_t EMB_OFF = 0;
    const size_t LOG_OFF = (size_t)N_NODES * NHID;
    const size_t PRB_OFF = LOG_OFF + (size_t)N_NODES * NCLASS;

    const float* er = &g_a[(size_t)node * NHID];
    float e0 = er[lane], e1 = er[lane + 32], e2 = er[lane + 64];
    esh[wid][lane] = e0; esh[wid][lane + 32] = e1; esh[wid][lane + 64] = e2;
    out[EMB_OFF + (size_t)node * NHID + lane]      = e0;
    out[EMB_OFF + (size_t)node * NHID + lane + 32] = e1;
    out[EMB_OFF + (size_t)node * NHID + lane + 64] = e2;
    __syncwarp();

    float l0 = -INFINITY, l1 = -INFINITY;
    if (lane < NCLASS) {
        float a = bs[lane];
#pragma unroll
        for (int k = 0; k < NHID; k++) a += esh[wid][k] * Ws[k * NCLASS + lane];
        l0 = a;
    }
    if (lane < NCLASS - 32) {  // lanes 0..7 handle cols 32..39
        float a = bs[lane + 32];
#pragma unroll
        for (int k = 0; k < NHID; k++) a += esh[wid][k] * Ws[k * NCLASS + lane + 32];
        l1 = a;
    }

    float m = fmaxf(l0, l1);
#pragma unroll
    for (int o = 16; o; o >>= 1) m = fmaxf(m, __shfl_xor_sync(0xFFFFFFFFu, m, o));
    float s = 0.f;
    float p0 = 0.f, p1 = 0.f;
    if (lane < NCLASS)      { p0 = expf(l0 - m); s += p0; }
    if (lane < NCLASS - 32) { p1 = expf(l1 - m); s += p1; }
#pragma unroll
    for (int o = 16; o; o >>= 1) s += __shfl_xor_sync(0xFFFFFFFFu, s, o);
    float invs = 1.0f / s;

    if (lane < NCLASS) {
        out[LOG_OFF + (size_t)node * NCLASS + lane] = l0;
        out[PRB_OFF + (size_t)node * NCLASS + lane] = p0 * invs;
    }
    if (lane < NCLASS - 32) {
        out[LOG_OFF + (size_t)node * NCLASS + lane + 32] = l1;
        out[PRB_OFF + (size_t)node * NCLASS + lane + 32] = p1 * invs;
    }
}

// ---------------------------------------------------------------------------
extern "C" void kernel_launch(void* const* d_in, const int* in_sizes, int n_in,
                              void* d_out, int out_size) {
    const float* x    = (const float*)d_in[0];
    const int*   ei   = (const int*)d_in[1];
    const float* ew   = (const float*)d_in[2];
    const float* W1   = (const float*)d_in[3];
    const float* b1   = (const float*)d_in[4];
    const float* W2   = (const float*)d_in[5];
    const float* b2   = (const float*)d_in[6];
    const float* W3   = (const float*)d_in[7];
    const float* b3   = (const float*)d_in[8];
    const float* linW = (const float*)d_in[9];
    const float* linb = (const float*)d_in[10];
    float* out = (float*)d_out;

    const int* src = ei;             // edge_index[0]
    const int* dst = ei + N_EDGES;   // edge_index[1]

    void* pa = nullptr;
    cudaGetSymbolAddress(&pa, g_a);
    const float* xa = (const float*)pa;

    dim3 gblk(24, 16);
    const int GEMM_GRID   = (N_NODES + 15) / 16;                 // 3125
    const int ZERO_GRID   = (N_NODES * NHID / 4 + 255) / 256;    // fill g_a
    const int SCAT_GRID   = (N_EDGES * 24 + 255) / 256;          // 75000
    const int NORM_GRID   = (N_NODES * 32 + 255) / 256;          // warp/node
    const int HEAD_GRID   = N_NODES / 4;                          // 12500

    // ---- Layer 1 (K = 128) ----
    gemm_kernel<NFEAT><<<GEMM_GRID, gblk>>>(x, W1);
    zero_agg_kernel<<<ZERO_GRID, 256>>>();
    scatter_kernel<<<SCAT_GRID, 256>>>(src, dst, ew);
    norm_kernel<<<NORM_GRID, 256>>>(b1);

    // ---- Layer 2 (K = 96) ----
    gemm_kernel<NHID><<<GEMM_GRID, gblk>>>(xa, W2);
    zero_agg_kernel<<<ZERO_GRID, 256>>>();
    scatter_kernel<<<SCAT_GRID, 256>>>(src, dst, ew);
    norm_kernel<<<NORM_GRID, 256>>>(b2);

    // ---- Layer 3 (K = 96) ----
    gemm_kernel<NHID><<<GEMM_GRID, gblk>>>(xa, W3);
    zero_agg_kernel<<<ZERO_GRID, 256>>>();
    scatter_kernel<<<SCAT_GRID, 256>>>(src, dst, ew);
    norm_kernel<<<NORM_GRID, 256>>>(b3);

    // ---- Head: emb copy + logits + softmax ----
    head_kernel<<<HEAD_GRID, 128>>>(linW, linb, out);
}

// round 2
// speedup vs baseline: 1.5096x; 1.5096x over previous
#include <cuda_runtime.h>
#include <cuda_bf16.h>
#include <math.h>

#define N_NODES 50000
#define N_EDGES 800000
#define NFEAT   128
#define NHID    96
#define NCLASS  40
#define NBLK_SCAN 196   // ceil(N_NODES/256)

// ---- static scratch (allocation-free) ----
__device__ __align__(16) float g_h[N_NODES * NHID];   // post-GEMM features
__device__ __align__(16) float g_a[N_NODES * NHID];   // post-aggregation features
__device__ int   g_cnt[N_NODES];
__device__ int   g_cnt2[N_NODES];
__device__ int   g_rowptr[N_NODES + 1];
__device__ int   g_blk[NBLK_SCAN];
__device__ int   g_blkoff[NBLK_SCAN];
__device__ int   g_ssrc[N_EDGES];
__device__ float g_sw[N_EDGES];

// ===========================================================================
// CSR build: zero -> histogram -> scan (3 kernels) -> placement
// ===========================================================================
__global__ void zero_cnt_kernel() {
    int i = blockIdx.x * blockDim.x + threadIdx.x;
    if (i < N_NODES) { g_cnt[i] = 0; g_cnt2[i] = 0; }
}

__global__ void hist_kernel(const int* __restrict__ dst) {
    int e = blockIdx.x * blockDim.x + threadIdx.x;
    if (e < N_EDGES) atomicAdd(&g_cnt[dst[e]], 1);
}

// chunk-level inclusive scan; writes exclusive-within-chunk to rowptr + chunk sum
__global__ void scan1_kernel() {
    __shared__ int sh[256];
    int t = threadIdx.x;
    int i = blockIdx.x * 256 + t;
    int c = (i < N_NODES) ? g_cnt[i] : 0;
    sh[t] = c;
    __syncthreads();
#pragma unroll
    for (int off = 1; off < 256; off <<= 1) {
        int v = (t >= off) ? sh[t - off] : 0;
        __syncthreads();
        sh[t] += v;
        __syncthreads();
    }
    if (i < N_NODES) g_rowptr[i] = sh[t] - c;   // exclusive within chunk
    if (t == 255) g_blk[blockIdx.x] = sh[255];
}

__global__ void scan2_kernel() {
    __shared__ int sh[256];
    int t = threadIdx.x;
    int c = (t < NBLK_SCAN) ? g_blk[t] : 0;
    sh[t] = c;
    __syncthreads();
#pragma unroll
    for (int off = 1; off < 256; off <<= 1) {
        int v = (t >= off) ? sh[t - off] : 0;
        __syncthreads();
        sh[t] += v;
        __syncthreads();
    }
    if (t < NBLK_SCAN) g_blkoff[t] = sh[t] - c; // exclusive across chunks
}

__global__ void scan3_kernel() {
    int i = blockIdx.x * blockDim.x + threadIdx.x;
    if (i < N_NODES) g_rowptr[i] += g_blkoff[i >> 8];
    if (i == 0) g_rowptr[N_NODES] = N_EDGES;
}

__global__ void place_kernel(const int* __restrict__ src,
                             const int* __restrict__ dst,
                             const float* __restrict__ ew) {
    int e = blockIdx.x * blockDim.x + threadIdx.x;
    if (e >= N_EDGES) return;
    int d = dst[e];
    int p = g_rowptr[d] + atomicAdd(&g_cnt2[d], 1);
    g_ssrc[p] = src[e];
    g_sw[p]   = ew[e];
}

// ===========================================================================
// GEMM: g_h[r,c] = sum_k X[r,k]*W[k,c]. Register-tiled 8x8 per thread.
// block (12,16) = 192 threads; tile = 128 rows x 96 cols; K-tiles of 32.
// ===========================================================================
template <int K>
__global__ void gemm_kernel(const float* __restrict__ X,
                            const float* __restrict__ W) {
    __shared__ float Xs[32][132];   // [k][row], padded stride vs bank conflicts
    __shared__ float Ws[32][96];    // [k][col]
    int tx = threadIdx.x;           // 0..11 -> cols tx*8..tx*8+7
    int ty = threadIdx.y;           // 0..15 -> rows ty*8..ty*8+7
    int tid = ty * 12 + tx;
    int rowBase = blockIdx.x * 128;

    float acc[8][8] = {};

    for (int kt = 0; kt < K; kt += 32) {
        // load X tile (transposed): 128 rows x 8 float4 along K
        for (int idx = tid; idx < 128 * 8; idx += 192) {
            int row = idx >> 3;
            int kc  = idx & 7;
            int gr = rowBase + row;
            if (gr >= N_NODES) gr = N_NODES - 1;   // clamp (stores guarded)
            float4 v = *reinterpret_cast<const float4*>(X + (size_t)gr * K + kt + kc * 4);
            Xs[kc * 4 + 0][row] = v.x;
            Xs[kc * 4 + 1][row] = v.y;
            Xs[kc * 4 + 2][row] = v.z;
            Xs[kc * 4 + 3][row] = v.w;
        }
        // load W tile: 32 x 96
        for (int idx = tid; idx < 32 * 24; idx += 192) {
            int kk = idx / 24;
            int cc = idx % 24;
            *reinterpret_cast<float4*>(&Ws[kk][cc * 4]) =
                *reinterpret_cast<const float4*>(W + (size_t)(kt + kk) * NHID + cc * 4);
        }
        __syncthreads();

#pragma unroll
        for (int k = 0; k < 32; k++) {
            float xr[8], wc[8];
            *reinterpret_cast<float4*>(&xr[0]) = *reinterpret_cast<float4*>(&Xs[k][ty * 8]);
            *reinterpret_cast<float4*>(&xr[4]) = *reinterpret_cast<float4*>(&Xs[k][ty * 8 + 4]);
            *reinterpret_cast<float4*>(&wc[0]) = *reinterpret_cast<float4*>(&Ws[k][tx * 8]);
            *reinterpret_cast<float4*>(&wc[4]) = *reinterpret_cast<float4*>(&Ws[k][tx * 8 + 4]);
#pragma unroll
            for (int i = 0; i < 8; i++)
#pragma unroll
                for (int j = 0; j < 8; j++)
                    acc[i][j] += xr[i] * wc[j];
        }
        __syncthreads();
    }

#pragma unroll
    for (int i = 0; i < 8; i++) {
        int gr = rowBase + ty * 8 + i;
        if (gr < N_NODES) {
            float4 v0 = make_float4(acc[i][0], acc[i][1], acc[i][2], acc[i][3]);
            float4 v1 = make_float4(acc[i][4], acc[i][5], acc[i][6], acc[i][7]);
            float* o = g_h + (size_t)gr * NHID + tx * 8;
            *reinterpret_cast<float4*>(o)     = v0;
            *reinterpret_cast<float4*>(o + 4) = v1;
        }
    }
}

// ===========================================================================
// CSR aggregation + bias + L2-normalize + ReLU. One warp per dst node.
// ===========================================================================
__global__ void agg_kernel(const float* __restrict__ bias) {
    int gw   = (blockIdx.x * blockDim.x + threadIdx.x) >> 5;
    int lane = threadIdx.x & 31;
    if (gw >= N_NODES) return;
    int beg = g_rowptr[gw], end = g_rowptr[gw + 1];

    float a0 = 0.f, a1 = 0.f, a2 = 0.f;
    int i = beg;
    for (; i + 1 < end; i += 2) {
        int   s0 = g_ssrc[i],  s1 = g_ssrc[i + 1];
        float w0 = g_sw[i],    w1 = g_sw[i + 1];
        const float* h0 = g_h + (size_t)s0 * NHID;
        const float* h1 = g_h + (size_t)s1 * NHID;
        a0 += w0 * h0[lane]      + w1 * h1[lane];
        a1 += w0 * h0[lane + 32] + w1 * h1[lane + 32];
        a2 += w0 * h0[lane + 64] + w1 * h1[lane + 64];
    }
    if (i < end) {
        int s0 = g_ssrc[i];
        float w0 = g_sw[i];
        const float* h0 = g_h + (size_t)s0 * NHID;
        a0 += w0 * h0[lane];
        a1 += w0 * h0[lane + 32];
        a2 += w0 * h0[lane + 64];
    }

    a0 += bias[lane]; a1 += bias[lane + 32]; a2 += bias[lane + 64];
    float s = a0 * a0 + a1 * a1 + a2 * a2;
#pragma unroll
    for (int o = 16; o; o >>= 1) s += __shfl_xor_sync(0xFFFFFFFFu, s, o);
    float inv = 1.0f / fmaxf(sqrtf(s), 1e-12f);

    float* row = g_a + (size_t)gw * NHID;
    row[lane]      = fmaxf(a0 * inv, 0.f);
    row[lane + 32] = fmaxf(a1 * inv, 0.f);
    row[lane + 64] = fmaxf(a2 * inv, 0.f);
}

// ===========================================================================
// Layer 3: aggregation + bias + norm + relu + emb out + logits + softmax.
// One warp per node, 8 warps/block.
// ===========================================================================
__global__ void agg_head_kernel(const float* __restrict__ bias,
                                const float* __restrict__ linW,
                                const float* __restrict__ linb,
                                float* __restrict__ out) {
    __shared__ float Ws[NHID * NCLASS];
    __shared__ float bs[NCLASS];
    __shared__ float esh[8][NHID];

    int tid = threadIdx.x;
    for (int i = tid; i < NHID * NCLASS; i += 256) Ws[i] = linW[i];
    if (tid < NCLASS) bs[tid] = linb[tid];
    __syncthreads();

    int wid  = tid >> 5;
    int lane = tid & 31;
    int node = blockIdx.x * 8 + wid;
    if (node >= N_NODES) return;

    int beg = g_rowptr[node], end = g_rowptr[node + 1];
    float a0 = 0.f, a1 = 0.f, a2 = 0.f;
    int i = beg;
    for (; i + 1 < end; i += 2) {
        int   s0 = g_ssrc[i],  s1 = g_ssrc[i + 1];
        float w0 = g_sw[i],    w1 = g_sw[i + 1];
        const float* h0 = g_h + (size_t)s0 * NHID;
        const float* h1 = g_h + (size_t)s1 * NHID;
        a0 += w0 * h0[lane]      + w1 * h1[lane];
        a1 += w0 * h0[lane + 32] + w1 * h1[lane + 32];
        a2 += w0 * h0[lane + 64] + w1 * h1[lane + 64];
    }
    if (i < end) {
        int s0 = g_ssrc[i];
        float w0 = g_sw[i];
        const float* h0 = g_h + (size_t)s0 * NHID;
        a0 += w0 * h0[lane];
        a1 += w0 * h0[lane + 32];
        a2 += w0 * h0[lane + 64];
    }

    a0 += bias[lane]; a1 += bias[lane + 32]; a2 += bias[lane + 64];
    float s = a0 * a0 + a1 * a1 + a2 * a2;
#pragma unroll
    for (int o = 16; o; o >>= 1) s += __shfl_xor_sync(0xFFFFFFFFu, s, o);
    float inv = 1.0f / fmaxf(sqrtf(s), 1e-12f);
    float e0 = fmaxf(a0 * inv, 0.f);
    float e1 = fmaxf(a1 * inv, 0.f);
    float e2 = fmaxf(a2 * inv, 0.f);

    const size_t EMB_OFF = 0;
    const size_t LOG_OFF = (size_t)N_NODES * NHID;
    const size_t PRB_OFF = LOG_OFF + (size_t)N_NODES * NCLASS;

    out[EMB_OFF + (size_t)node * NHID + lane]      = e0;
    out[EMB_OFF + (size_t)node * NHID + lane + 32] = e1;
    out[EMB_OFF + (size_t)node * NHID + lane + 64] = e2;
    esh[wid][lane] = e0; esh[wid][lane + 32] = e1; esh[wid][lane + 64] = e2;
    __syncwarp();

    float l0 = -INFINITY, l1 = -INFINITY;
    if (lane < NCLASS) {
        float a = bs[lane];
#pragma unroll
        for (int k = 0; k < NHID; k++) a += esh[wid][k] * Ws[k * NCLASS + lane];
        l0 = a;
    }
    if (lane < NCLASS - 32) {
        float a = bs[lane + 32];
#pragma unroll
        for (int k = 0; k < NHID; k++) a += esh[wid][k] * Ws[k * NCLASS + lane + 32];
        l1 = a;
    }

    float m = fmaxf(l0, l1);
#pragma unroll
    for (int o = 16; o; o >>= 1) m = fmaxf(m, __shfl_xor_sync(0xFFFFFFFFu, m, o));
    float sum = 0.f, p0 = 0.f, p1 = 0.f;
    if (lane < NCLASS)      { p0 = expf(l0 - m); sum += p0; }
    if (lane < NCLASS - 32) { p1 = expf(l1 - m); sum += p1; }
#pragma unroll
    for (int o = 16; o; o >>= 1) sum += __shfl_xor_sync(0xFFFFFFFFu, sum, o);
    float invs = 1.0f / sum;

    if (lane < NCLASS) {
        out[LOG_OFF + (size_t)node * NCLASS + lane] = l0;
        out[PRB_OFF + (size_t)node * NCLASS + lane] = p0 * invs;
    }
    if (lane < NCLASS - 32) {
        out[LOG_OFF + (size_t)node * NCLASS + lane + 32] = l1;
        out[PRB_OFF + (size_t)node * NCLASS + lane + 32] = p1 * invs;
    }
}

// ===========================================================================
extern "C" void kernel_launch(void* const* d_in, const int* in_sizes, int n_in,
                              void* d_out, int out_size) {
    const float* x    = (const float*)d_in[0];
    const int*   ei   = (const int*)d_in[1];
    const float* ew   = (const float*)d_in[2];
    const float* W1   = (const float*)d_in[3];
    const float* b1   = (const float*)d_in[4];
    const float* W2   = (const float*)d_in[5];
    const float* b2   = (const float*)d_in[6];
    const float* W3   = (const float*)d_in[7];
    const float* b3   = (const float*)d_in[8];
    const float* linW = (const float*)d_in[9];
    const float* linb = (const float*)d_in[10];
    float* out = (float*)d_out;

    const int* src = ei;
    const int* dst = ei + N_EDGES;

    void* pa = nullptr;
    cudaGetSymbolAddress(&pa, g_a);
    const float* xa = (const float*)pa;

    const int EDGE_GRID = (N_EDGES + 255) / 256;     // 3125
    const int NODE_GRID = (N_NODES + 255) / 256;     // 196
    const int GEMM_GRID = (N_NODES + 127) / 128;     // 391
    const int AGG_GRID  = (N_NODES * 32 + 255) / 256;// warp/node, 6250
    dim3 gblk(12, 16);

    // ---- CSR build (per replay) ----
    zero_cnt_kernel<<<NODE_GRID, 256>>>();
    hist_kernel<<<EDGE_GRID, 256>>>(dst);
    scan1_kernel<<<NBLK_SCAN, 256>>>();
    scan2_kernel<<<1, 256>>>();
    scan3_kernel<<<NODE_GRID, 256>>>();
    place_kernel<<<EDGE_GRID, 256>>>(src, dst, ew);

    // ---- Layer 1 ----
    gemm_kernel<NFEAT><<<GEMM_GRID, gblk>>>(x, W1);
    agg_kernel<<<AGG_GRID, 256>>>(b1);
    // ---- Layer 2 ----
    gemm_kernel<NHID><<<GEMM_GRID, gblk>>>(xa, W2);
    agg_kernel<<<AGG_GRID, 256>>>(b2);
    // ---- Layer 3 + head ----
    gemm_kernel<NHID><<<GEMM_GRID, gblk>>>(xa, W3);
    agg_head_kernel<<<(N_NODES + 7) / 8, 256>>>(b3, linW, linb, out);
}